// round 1
// baseline (speedup 1.0000x reference)
#include <cuda_runtime.h>
#include <cuda_bf16.h>

#define BB 16
#define CC 512
#define MM 256
#define HWN 4096
#define ATTN 32

// ---------------- scratch (device globals; no allocation allowed) ----------------
__device__ float g_Y[BB*CC];      // sum_h x * exp(l)
__device__ float g_S[BB];         // sum_h exp(l)
__device__ float g_Gmax[BB*MM];   // max_h W_ql x
__device__ float g_v[BB*CC];      // W_vl^T avg
__device__ float g_c0[BB];
__device__ float g_P[BB*CC];
__device__ float g_Q[BB*CC];
__device__ float g_E[BB*HWN];     // exp(ctx)
__device__ float g_Esum[BB];

__device__ __forceinline__ void atomicMaxF(float* addr, float v) {
    int old = __float_as_int(*addr);
    while (__int_as_float(old) < v) {
        int prev = atomicCAS((int*)addr, old, __float_as_int(v));
        if (prev == old) break;
        old = prev;
    }
}

// ---------------- K0: init accumulators (graph replays need re-init) ----------------
__global__ void k0_init() {
    int i = blockIdx.x * 256 + threadIdx.x;
    if (i < BB*CC) g_Y[i] = 0.f;
    if (i < BB*MM) g_Gmax[i] = __int_as_float(0xff800000u); // -inf
    if (i < BB) { g_S[i] = 0.f; g_Esum[i] = 0.f; }
}

// ---------------- K1: mask logits, exp, weighted-x accumulation ----------------
// grid (B, 16), 256 threads, 256 pixels per CTA
__global__ void k1_mask_y(const float* __restrict__ x,
                          const float* __restrict__ w_qr,
                          const float* __restrict__ b_qr) {
    __shared__ float sw[CC];
    __shared__ float se[256];
    __shared__ float sred[256];
    int b = blockIdx.x, chunk = blockIdx.y, t = threadIdx.x;
    for (int i = t; i < CC; i += 256) sw[i] = w_qr[i];
    __syncthreads();

    int h = chunk * 256 + t;
    const float* xb = x + (size_t)b * CC * HWN;
    float l = b_qr[0];
#pragma unroll 8
    for (int c = 0; c < CC; c++) l += sw[c] * xb[c * HWN + h];
    float e = expf(l);   // no max-subtract: |l| <= ~6, exp safe; ratios identical
    se[t] = e;
    sred[t] = e;
    __syncthreads();
    for (int s = 128; s > 0; s >>= 1) { if (t < s) sred[t] += sred[t + s]; __syncthreads(); }
    if (t == 0) atomicAdd(&g_S[b], sred[0]);

    // y[c] += sum_j e_j * x[c, h0+j]
    const float4* se4 = (const float4*)se;
    for (int cc = t; cc < CC; cc += 256) {
        const float4* xr = (const float4*)(xb + (size_t)cc * HWN + chunk * 256);
        float acc = 0.f;
#pragma unroll 8
        for (int j = 0; j < 64; j++) {
            float4 xv = xr[j]; float4 ev = se4[j];
            acc += ev.x*xv.x + ev.y*xv.y + ev.z*xv.z + ev.w*xv.w;
        }
        atomicAdd(&g_Y[b*CC + cc], acc);
    }
}

// ---------------- K2: g_max = max_h (W_ql @ x)  via bf16 mma.sync ----------------
// grid (B, 32): each CTA does full M=256 x 128-pixel tile, K=512.
// 8 warps arranged 4(m) x 2(n): warp tile 64x64. m16n8k16 bf16 -> f32.
__global__ __launch_bounds__(256) void k2_gmax(const float* __restrict__ x,
                                               const float* __restrict__ w_ql) {
    __shared__ __nv_bfloat16 As[MM][40];   // pad 40: conflict-free frag loads
    __shared__ __nv_bfloat16 Bs[128][40];
    int b = blockIdx.x, nt = blockIdx.y, t = threadIdx.x;
    int warp = t >> 5, lane = t & 31;
    int wm = warp >> 1, wn = warp & 1;
    int n0 = nt * 128;
    const float* xb = x + (size_t)b * CC * HWN + n0;

    float acc[4][8][4];
#pragma unroll
    for (int i = 0; i < 4; i++)
#pragma unroll
        for (int j = 0; j < 8; j++)
#pragma unroll
            for (int k = 0; k < 4; k++) acc[i][j][k] = 0.f;

    for (int k0 = 0; k0 < CC; k0 += 32) {
        __syncthreads();
#pragma unroll
        for (int p = 0; p < 32; p++) {          // A: 256x32
            int i = t + p * 256;
            int m = i >> 5, k = i & 31;
            As[m][k] = __float2bfloat16(w_ql[m * CC + k0 + k]);
        }
#pragma unroll
        for (int p = 0; p < 16; p++) {          // B: 32x128 -> Bs[n][k]
            int i = t + p * 256;
            int n = i & 127, k = i >> 7;
            Bs[n][k] = __float2bfloat16(xb[(size_t)(k0 + k) * HWN + n]);
        }
        __syncthreads();
#pragma unroll
        for (int kb = 0; kb < 32; kb += 16) {
            unsigned af[4][4], bf[8][2];
#pragma unroll
            for (int mf = 0; mf < 4; mf++) {
                int r = wm * 64 + mf * 16 + (lane >> 2);
                int cq = kb + (lane & 3) * 2;
                af[mf][0] = *(const unsigned*)&As[r][cq];
                af[mf][1] = *(const unsigned*)&As[r + 8][cq];
                af[mf][2] = *(const unsigned*)&As[r][cq + 8];
                af[mf][3] = *(const unsigned*)&As[r + 8][cq + 8];
            }
#pragma unroll
            for (int nf = 0; nf < 8; nf++) {
                int n = wn * 64 + nf * 8 + (lane >> 2);
                int cq = kb + (lane & 3) * 2;
                bf[nf][0] = *(const unsigned*)&Bs[n][cq];
                bf[nf][1] = *(const unsigned*)&Bs[n][cq + 8];
            }
#pragma unroll
            for (int mf = 0; mf < 4; mf++)
#pragma unroll
                for (int nf = 0; nf < 8; nf++)
                    asm volatile(
                        "mma.sync.aligned.m16n8k16.row.col.f32.bf16.bf16.f32 "
                        "{%0,%1,%2,%3}, {%4,%5,%6,%7}, {%8,%9}, {%0,%1,%2,%3};\n"
                        : "+f"(acc[mf][nf][0]), "+f"(acc[mf][nf][1]),
                          "+f"(acc[mf][nf][2]), "+f"(acc[mf][nf][3])
                        : "r"(af[mf][0]), "r"(af[mf][1]), "r"(af[mf][2]), "r"(af[mf][3]),
                          "r"(bf[nf][0]), "r"(bf[nf][1]));
        }
    }
    // row-max over this CTA's 128 pixels, then global atomic max
#pragma unroll
    for (int mf = 0; mf < 4; mf++) {
        float m0 = __int_as_float(0xff800000u), m1 = m0;
#pragma unroll
        for (int nf = 0; nf < 8; nf++) {
            m0 = fmaxf(m0, fmaxf(acc[mf][nf][0], acc[mf][nf][1]));
            m1 = fmaxf(m1, fmaxf(acc[mf][nf][2], acc[mf][nf][3]));
        }
        m0 = fmaxf(m0, __shfl_xor_sync(0xffffffffu, m0, 1));
        m0 = fmaxf(m0, __shfl_xor_sync(0xffffffffu, m0, 2));
        m1 = fmaxf(m1, __shfl_xor_sync(0xffffffffu, m1, 1));
        m1 = fmaxf(m1, __shfl_xor_sync(0xffffffffu, m1, 2));
        if ((lane & 3) == 0) {
            int r = wm * 64 + mf * 16 + (lane >> 2);
            atomicMaxF(&g_Gmax[b * MM + r], m0);
            atomicMaxF(&g_Gmax[b * MM + r + 8], m1);
        }
    }
}

// ---------------- K3: all the tiny per-batch math ----------------
// grid B, 256 threads
__global__ void k3_small(const float* __restrict__ w_vr, const float* __restrict__ b_vr,
                         const float* __restrict__ w_up, const float* __restrict__ b_up,
                         const float* __restrict__ ln_g, const float* __restrict__ ln_b,
                         const float* __restrict__ b_ql,
                         const float* __restrict__ w_vl, const float* __restrict__ b_vl,
                         const float* __restrict__ w_red, const float* __restrict__ bn_g,
                         const float* __restrict__ bn_b, const float* __restrict__ bn_rm,
                         const float* __restrict__ bn_rv, const float* __restrict__ w_sel) {
    __shared__ float sy[CC];
    __shared__ float sctx[MM];
    __shared__ float sca[CC];
    __shared__ float savg[MM];
    __shared__ float ssk[ATTN];
    __shared__ float red_buf[256];
    int b = blockIdx.x, t = threadIdx.x;

    float Sinv = 1.f / g_S[b];
    for (int c = t; c < CC; c += 256) sy[c] = g_Y[b*CC + c] * Sinv;
    __syncthreads();

    // context = W_vr y + b_vr
    {
        float a = b_vr[t];
        const float* wr = w_vr + (size_t)t * CC;
        for (int c = 0; c < CC; c++) a += wr[c] * sy[c];
        sctx[t] = a;
    }
    __syncthreads();

    // up = W_up context + b_up
    float upv[2];
    for (int i = 0; i < 2; i++) {
        int c = t + i * 256;
        float a = b_up[c];
        const float* wr = w_up + (size_t)c * MM;
        for (int m = 0; m < MM; m++) a += wr[m] * sctx[m];
        upv[i] = a;
    }
    // LayerNorm over 512
    red_buf[t] = upv[0] + upv[1];
    __syncthreads();
    for (int s = 128; s > 0; s >>= 1) { if (t < s) red_buf[t] += red_buf[t + s]; __syncthreads(); }
    float mean = red_buf[0] / CC;
    __syncthreads();
    red_buf[t] = upv[0]*upv[0] + upv[1]*upv[1];
    __syncthreads();
    for (int s = 128; s > 0; s >>= 1) { if (t < s) red_buf[t] += red_buf[t + s]; __syncthreads(); }
    float var = red_buf[0] / CC - mean * mean;
    float rstd = rsqrtf(var + 1e-5f);
    __syncthreads();
    for (int i = 0; i < 2; i++) {
        int c = t + i * 256;
        float ln = (upv[i] - mean) * rstd * ln_g[c] + ln_b[c];
        sca[c] = 1.f / (1.f + expf(-ln));
    }
    __syncthreads();

    // avg = softmax(Gmax + b_ql) over 256
    float gv = g_Gmax[b*MM + t] + b_ql[t];
    red_buf[t] = gv; __syncthreads();
    for (int s = 128; s > 0; s >>= 1) { if (t < s) red_buf[t] = fmaxf(red_buf[t], red_buf[t+s]); __syncthreads(); }
    float gm = red_buf[0];
    __syncthreads();
    float ge = expf(gv - gm);
    red_buf[t] = ge; __syncthreads();
    for (int s = 128; s > 0; s >>= 1) { if (t < s) red_buf[t] += red_buf[t + s]; __syncthreads(); }
    savg[t] = ge / red_buf[0];
    __syncthreads();

    // v = W_vl^T avg (coalesced: for fixed m, consecutive c across threads)
    for (int i = 0; i < 2; i++) {
        int c = t + i * 256;
        float a = 0.f;
        for (int m = 0; m < MM; m++) a += savg[m] * w_vl[(size_t)m * CC + c];
        g_v[b*CC + c] = a;
    }
    red_buf[t] = savg[t] * b_vl[t]; __syncthreads();
    for (int s = 128; s > 0; s >>= 1) { if (t < s) red_buf[t] += red_buf[t + s]; __syncthreads(); }
    if (t == 0) g_c0[b] = red_buf[0];
    __syncthreads();

    // SelectiveKernelAttn: s[c] = ca*(1+1/HW) + 1/HW  (mean of spatial softmax = 1/HW exactly)
    const float invHW = 1.f / (float)HWN;
    for (int i = 0; i < 2; i++) { int c = t + i*256; sy[c] = sca[c] * (1.f + invHW) + invHW; }
    __syncthreads();
    if (t < ATTN) {
        float a = 0.f;
        const float* wr = w_red + (size_t)t * CC;
        for (int c = 0; c < CC; c++) a += wr[c] * sy[c];
        a = (a - bn_rm[t]) * rsqrtf(bn_rv[t] + 1e-5f) * bn_g[t] + bn_b[t];
        ssk[t] = fmaxf(a, 0.f);
    }
    __syncthreads();
    for (int i = 0; i < 2; i++) {
        int c = t + i * 256;
        float s0 = 0.f, s1 = 0.f;
        const float* w0 = w_sel + (size_t)c * ATTN;
        const float* w1 = w_sel + (size_t)(CC + c) * ATTN;
#pragma unroll
        for (int a = 0; a < ATTN; a++) { s0 += w0[a] * ssk[a]; s1 += w1[a] * ssk[a]; }
        float mx = fmaxf(s0, s1);
        float e0 = expf(s0 - mx), e1 = expf(s1 - mx);
        float inv = 1.f / (e0 + e1);
        float a0 = e0 * inv, a1 = e1 * inv;
        float ca = sca[c];
        g_P[b*CC + c] = a0 * ca + a1;   // coeff of spatial_attn
        g_Q[b*CC + c] = a1 * ca;        // constant part
    }
}

// ---------------- K4: ctx per pixel = v . x + c0 ; exp & sum ----------------
__global__ void k4_ctx(const float* __restrict__ x) {
    __shared__ float sv[CC];
    __shared__ float red[256];
    int b = blockIdx.x, chunk = blockIdx.y, t = threadIdx.x;
    for (int i = t; i < CC; i += 256) sv[i] = g_v[b*CC + i];
    __syncthreads();
    int h = chunk * 256 + t;
    const float* xb = x + (size_t)b * CC * HWN;
    float a = g_c0[b];
#pragma unroll 8
    for (int c = 0; c < CC; c++) a += sv[c] * xb[c * HWN + h];
    float e = expf(a);   // |ctx| <= ~6, safe
    g_E[b*HWN + h] = e;
    red[t] = e; __syncthreads();
    for (int s = 128; s > 0; s >>= 1) { if (t < s) red[t] += red[t + s]; __syncthreads(); }
    if (t == 0) atomicAdd(&g_Esum[b], red[0]);
}

// ---------------- K5: out = x * (1 + Q + P * spatial_attn) ----------------
__global__ void k5_final(const float* __restrict__ x, float* __restrict__ out) {
    int i4 = blockIdx.x * 256 + threadIdx.x;           // float4 index
    int h4 = i4 & 1023;                                // HW/4 = 1024
    int c  = (i4 >> 10) & 511;
    int b  = i4 >> 19;
    float4 xv = ((const float4*)x)[i4];
    float4 ev = ((const float4*)g_E)[b * (HWN/4) + h4];
    float inv = 1.f / g_Esum[b];
    float P = g_P[b*CC + c], Q = g_Q[b*CC + c];
    float base = 1.f + Q;
    float4 o;
    o.x = xv.x * (base + P * ev.x * inv);
    o.y = xv.y * (base + P * ev.y * inv);
    o.z = xv.z * (base + P * ev.z * inv);
    o.w = xv.w * (base + P * ev.w * inv);
    ((float4*)out)[i4] = o;
}

// ---------------- launch ----------------
extern "C" void kernel_launch(void* const* d_in, const int* in_sizes, int n_in,
                              void* d_out, int out_size) {
    const float* x     = (const float*)d_in[0];
    const float* w_qr  = (const float*)d_in[1];
    const float* b_qr  = (const float*)d_in[2];
    const float* w_vr  = (const float*)d_in[3];
    const float* b_vr  = (const float*)d_in[4];
    const float* w_up  = (const float*)d_in[5];
    const float* b_up  = (const float*)d_in[6];
    const float* ln_g  = (const float*)d_in[7];
    const float* ln_b  = (const float*)d_in[8];
    const float* w_ql  = (const float*)d_in[9];
    const float* b_ql  = (const float*)d_in[10];
    const float* w_vl  = (const float*)d_in[11];
    const float* b_vl  = (const float*)d_in[12];
    const float* w_red = (const float*)d_in[13];
    const float* bn_g  = (const float*)d_in[14];
    const float* bn_b  = (const float*)d_in[15];
    const float* bn_rm = (const float*)d_in[16];
    const float* bn_rv = (const float*)d_in[17];
    const float* w_sel = (const float*)d_in[18];
    float* out = (float*)d_out;

    k0_init<<<32, 256>>>();
    k1_mask_y<<<dim3(BB, 16), 256>>>(x, w_qr, b_qr);
    k2_gmax<<<dim3(BB, 32), 256>>>(x, w_ql);
    k3_small<<<BB, 256>>>(w_vr, b_vr, w_up, b_up, ln_g, ln_b, b_ql,
                          w_vl, b_vl, w_red, bn_g, bn_b, bn_rm, bn_rv, w_sel);
    k4_ctx<<<dim3(BB, 16), 256>>>(x);
    k5_final<<<(BB*CC*HWN/4)/256, 256>>>(x, out);
}

// round 2
// speedup vs baseline: 1.2402x; 1.2402x over previous
#include <cuda_runtime.h>
#include <cuda_bf16.h>

#define BB 16
#define CC 512
#define MM 256
#define HWN 4096
#define ATTN 32

// ---------------- scratch (device globals; no allocation allowed) ----------------
__device__ float g_Y[BB*CC];      // sum_h x * exp(l)
__device__ float g_S[BB];         // sum_h exp(l)
__device__ float g_Gmax[BB*MM];   // max_h W_ql x
__device__ float g_v[BB*CC];      // W_vl^T avg
__device__ float g_c0[BB];
__device__ float g_P[BB*CC];
__device__ float g_Q[BB*CC];
__device__ float g_E[BB*HWN];     // exp(ctx)
__device__ float g_Esum[BB];

__device__ __forceinline__ void atomicMaxF(float* addr, float v) {
    int old = __float_as_int(*addr);
    while (__int_as_float(old) < v) {
        int prev = atomicCAS((int*)addr, old, __float_as_int(v));
        if (prev == old) break;
        old = prev;
    }
}

// block-wide reductions for 256 threads (8 warps)
__device__ __forceinline__ float blockSum256(float v, float* red) {
    int t = threadIdx.x, lane = t & 31, warp = t >> 5;
    __syncthreads();                       // protect red[] from previous use
#pragma unroll
    for (int o = 16; o; o >>= 1) v += __shfl_xor_sync(~0u, v, o);
    if (lane == 0) red[warp] = v;
    __syncthreads();
    if (warp == 0) {
        float s = (lane < 8) ? red[lane] : 0.f;
#pragma unroll
        for (int o = 4; o; o >>= 1) s += __shfl_xor_sync(~0u, s, o);
        if (lane == 0) red[0] = s;
    }
    __syncthreads();
    return red[0];
}
__device__ __forceinline__ float blockMax256(float v, float* red) {
    int t = threadIdx.x, lane = t & 31, warp = t >> 5;
    __syncthreads();
#pragma unroll
    for (int o = 16; o; o >>= 1) v = fmaxf(v, __shfl_xor_sync(~0u, v, o));
    if (lane == 0) red[warp] = v;
    __syncthreads();
    if (warp == 0) {
        float s = (lane < 8) ? red[lane] : __int_as_float(0xff800000u);
#pragma unroll
        for (int o = 4; o; o >>= 1) s = fmaxf(s, __shfl_xor_sync(~0u, s, o));
        if (lane == 0) red[0] = s;
    }
    __syncthreads();
    return red[0];
}

// ---------------- K0: init accumulators (graph replays need re-init) ----------------
__global__ void k0_init() {
    int i = blockIdx.x * 256 + threadIdx.x;
    if (i < BB*CC) g_Y[i] = 0.f;
    if (i < BB*MM) g_Gmax[i] = __int_as_float(0xff800000u); // -inf
    if (i < BB) { g_S[i] = 0.f; g_Esum[i] = 0.f; }
}

// ---------------- K1: mask logits, exp, weighted-x accumulation ----------------
// grid (B, 16), 256 threads, 256 pixels per CTA
__global__ void k1_mask_y(const float* __restrict__ x,
                          const float* __restrict__ w_qr,
                          const float* __restrict__ b_qr) {
    __shared__ float sw[CC];
    __shared__ float se[256];
    __shared__ float sred[256];
    int b = blockIdx.x, chunk = blockIdx.y, t = threadIdx.x;
    for (int i = t; i < CC; i += 256) sw[i] = w_qr[i];
    __syncthreads();

    int h = chunk * 256 + t;
    const float* xb = x + (size_t)b * CC * HWN;
    float l = b_qr[0];
#pragma unroll 8
    for (int c = 0; c < CC; c++) l += sw[c] * xb[c * HWN + h];
    float e = expf(l);   // no max-subtract: |l| <= ~6, exp safe; ratios identical
    se[t] = e;
    sred[t] = e;
    __syncthreads();
    for (int s = 128; s > 0; s >>= 1) { if (t < s) sred[t] += sred[t + s]; __syncthreads(); }
    if (t == 0) atomicAdd(&g_S[b], sred[0]);

    // y[c] += sum_j e_j * x[c, h0+j]
    const float4* se4 = (const float4*)se;
    for (int cc = t; cc < CC; cc += 256) {
        const float4* xr = (const float4*)(xb + (size_t)cc * HWN + chunk * 256);
        float acc = 0.f;
#pragma unroll 8
        for (int j = 0; j < 64; j++) {
            float4 xv = xr[j]; float4 ev = se4[j];
            acc += ev.x*xv.x + ev.y*xv.y + ev.z*xv.z + ev.w*xv.w;
        }
        atomicAdd(&g_Y[b*CC + cc], acc);
    }
}

// ---------------- K2: g_max = max_h (W_ql @ x)  via bf16 mma.sync ----------------
// grid (B, 32): each CTA does full M=256 x 128-pixel tile, K=512.
// 8 warps arranged 4(m) x 2(n): warp tile 64x64. m16n8k16 bf16 -> f32.
__global__ __launch_bounds__(256) void k2_gmax(const float* __restrict__ x,
                                               const float* __restrict__ w_ql) {
    __shared__ __nv_bfloat16 As[MM][40];   // pad 40: conflict-free frag loads
    __shared__ __nv_bfloat16 Bs[128][40];
    int b = blockIdx.x, nt = blockIdx.y, t = threadIdx.x;
    int warp = t >> 5, lane = t & 31;
    int wm = warp >> 1, wn = warp & 1;
    int n0 = nt * 128;
    const float* xb = x + (size_t)b * CC * HWN + n0;

    float acc[4][8][4];
#pragma unroll
    for (int i = 0; i < 4; i++)
#pragma unroll
        for (int j = 0; j < 8; j++)
#pragma unroll
            for (int k = 0; k < 4; k++) acc[i][j][k] = 0.f;

    for (int k0 = 0; k0 < CC; k0 += 32) {
        __syncthreads();
#pragma unroll
        for (int p = 0; p < 32; p++) {          // A: 256x32
            int i = t + p * 256;
            int m = i >> 5, k = i & 31;
            As[m][k] = __float2bfloat16(w_ql[m * CC + k0 + k]);
        }
#pragma unroll
        for (int p = 0; p < 16; p++) {          // B: 32x128 -> Bs[n][k]
            int i = t + p * 256;
            int n = i & 127, k = i >> 7;
            Bs[n][k] = __float2bfloat16(xb[(size_t)(k0 + k) * HWN + n]);
        }
        __syncthreads();
#pragma unroll
        for (int kb = 0; kb < 32; kb += 16) {
            unsigned af[4][4], bf[8][2];
#pragma unroll
            for (int mf = 0; mf < 4; mf++) {
                int r = wm * 64 + mf * 16 + (lane >> 2);
                int cq = kb + (lane & 3) * 2;
                af[mf][0] = *(const unsigned*)&As[r][cq];
                af[mf][1] = *(const unsigned*)&As[r + 8][cq];
                af[mf][2] = *(const unsigned*)&As[r][cq + 8];
                af[mf][3] = *(const unsigned*)&As[r + 8][cq + 8];
            }
#pragma unroll
            for (int nf = 0; nf < 8; nf++) {
                int n = wn * 64 + nf * 8 + (lane >> 2);
                int cq = kb + (lane & 3) * 2;
                bf[nf][0] = *(const unsigned*)&Bs[n][cq];
                bf[nf][1] = *(const unsigned*)&Bs[n][cq + 8];
            }
#pragma unroll
            for (int mf = 0; mf < 4; mf++)
#pragma unroll
                for (int nf = 0; nf < 8; nf++)
                    asm volatile(
                        "mma.sync.aligned.m16n8k16.row.col.f32.bf16.bf16.f32 "
                        "{%0,%1,%2,%3}, {%4,%5,%6,%7}, {%8,%9}, {%0,%1,%2,%3};\n"
                        : "+f"(acc[mf][nf][0]), "+f"(acc[mf][nf][1]),
                          "+f"(acc[mf][nf][2]), "+f"(acc[mf][nf][3])
                        : "r"(af[mf][0]), "r"(af[mf][1]), "r"(af[mf][2]), "r"(af[mf][3]),
                          "r"(bf[nf][0]), "r"(bf[nf][1]));
        }
    }
    // row-max over this CTA's 128 pixels, then global atomic max
#pragma unroll
    for (int mf = 0; mf < 4; mf++) {
        float m0 = __int_as_float(0xff800000u), m1 = m0;
#pragma unroll
        for (int nf = 0; nf < 8; nf++) {
            m0 = fmaxf(m0, fmaxf(acc[mf][nf][0], acc[mf][nf][1]));
            m1 = fmaxf(m1, fmaxf(acc[mf][nf][2], acc[mf][nf][3]));
        }
        m0 = fmaxf(m0, __shfl_xor_sync(0xffffffffu, m0, 1));
        m0 = fmaxf(m0, __shfl_xor_sync(0xffffffffu, m0, 2));
        m1 = fmaxf(m1, __shfl_xor_sync(0xffffffffu, m1, 1));
        m1 = fmaxf(m1, __shfl_xor_sync(0xffffffffu, m1, 2));
        if ((lane & 3) == 0) {
            int r = wm * 64 + mf * 16 + (lane >> 2);
            atomicMaxF(&g_Gmax[b * MM + r], m0);
            atomicMaxF(&g_Gmax[b * MM + r + 8], m1);
        }
    }
}

// ---------------- K3: all the tiny per-batch math (warp-cooperative GEMVs) ----------------
// grid B, 256 threads
__global__ void k3_small(const float* __restrict__ w_vr, const float* __restrict__ b_vr,
                         const float* __restrict__ w_up, const float* __restrict__ b_up,
                         const float* __restrict__ ln_g, const float* __restrict__ ln_b,
                         const float* __restrict__ b_ql,
                         const float* __restrict__ w_vl, const float* __restrict__ b_vl,
                         const float* __restrict__ w_red, const float* __restrict__ bn_g,
                         const float* __restrict__ bn_b, const float* __restrict__ bn_rm,
                         const float* __restrict__ bn_rv, const float* __restrict__ w_sel) {
    __shared__ float sy[CC];
    __shared__ float sctx[MM];
    __shared__ float sup[CC];
    __shared__ float sca[CC];
    __shared__ float savg[MM];
    __shared__ float ssk[ATTN];
    __shared__ float red[8];
    int b = blockIdx.x, t = threadIdx.x;
    int warp = t >> 5, lane = t & 31;

    float Sinv = 1.f / g_S[b];
    for (int c = t; c < CC; c += 256) sy[c] = g_Y[b*CC + c] * Sinv;
    __syncthreads();

    // context[m] = W_vr[m,:].sy + b_vr : warp per 32 rows, lanes over c (coalesced)
#pragma unroll 2
    for (int i = 0; i < 32; i++) {
        int r = warp * 32 + i;
        const float* wr = w_vr + (size_t)r * CC;
        float a = 0.f;
#pragma unroll
        for (int c = lane; c < CC; c += 32) a += wr[c] * sy[c];
#pragma unroll
        for (int o = 16; o; o >>= 1) a += __shfl_xor_sync(~0u, a, o);
        if (lane == 0) sctx[r] = a + b_vr[r];
    }
    __syncthreads();

    // up[c] = W_up[c,:].sctx + b_up : warp per 64 rows
#pragma unroll 2
    for (int i = 0; i < 64; i++) {
        int r = warp * 64 + i;
        const float* wr = w_up + (size_t)r * MM;
        float a = 0.f;
#pragma unroll
        for (int m = lane; m < MM; m += 32) a += wr[m] * sctx[m];
#pragma unroll
        for (int o = 16; o; o >>= 1) a += __shfl_xor_sync(~0u, a, o);
        if (lane == 0) sup[r] = a + b_up[r];
    }
    __syncthreads();

    // LayerNorm over 512 + sigmoid
    float u0 = sup[t], u1 = sup[t + 256];
    float mean = blockSum256(u0 + u1, red) * (1.f / CC);
    float var  = blockSum256(u0*u0 + u1*u1, red) * (1.f / CC) - mean * mean;
    float rstd = rsqrtf(var + 1e-5f);
    {
        float ln0 = (u0 - mean) * rstd * ln_g[t] + ln_b[t];
        float ln1 = (u1 - mean) * rstd * ln_g[t + 256] + ln_b[t + 256];
        sca[t]       = 1.f / (1.f + expf(-ln0));
        sca[t + 256] = 1.f / (1.f + expf(-ln1));
    }

    // avg = softmax(Gmax + b_ql) over 256  (t indexes the 256 elements directly)
    float gv = g_Gmax[b*MM + t] + b_ql[t];
    float gm = blockMax256(gv, red);
    float ge = expf(gv - gm);
    float gs = blockSum256(ge, red);
    savg[t] = ge / gs;
    float c0 = blockSum256((ge / gs) * b_vl[t], red);
    if (t == 0) g_c0[b] = c0;
    __syncthreads();

    // v[c] = sum_m avg[m] * w_vl[m,c]  (coalesced across c)
    {
        float a0 = 0.f, a1 = 0.f;
#pragma unroll 8
        for (int m = 0; m < MM; m++) {
            float av = savg[m];
            const float* wr = w_vl + (size_t)m * CC;
            a0 += av * wr[t];
            a1 += av * wr[t + 256];
        }
        g_v[b*CC + t]       = a0;
        g_v[b*CC + t + 256] = a1;
    }

    // SelectiveKernelAttn: s[c] = ca*(1+1/HW) + 1/HW
    const float invHW = 1.f / (float)HWN;
    sy[t]       = sca[t]       * (1.f + invHW) + invHW;
    sy[t + 256] = sca[t + 256] * (1.f + invHW) + invHW;
    __syncthreads();

    // red = relu(bn(W_red s)) : warp per 4 rows
#pragma unroll
    for (int i = 0; i < 4; i++) {
        int r = warp * 4 + i;
        const float* wr = w_red + (size_t)r * CC;
        float a = 0.f;
#pragma unroll
        for (int c = lane; c < CC; c += 32) a += wr[c] * sy[c];
#pragma unroll
        for (int o = 16; o; o >>= 1) a += __shfl_xor_sync(~0u, a, o);
        if (lane == 0) {
            a = (a - bn_rm[r]) * rsqrtf(bn_rv[r] + 1e-5f) * bn_g[r] + bn_b[r];
            ssk[r] = fmaxf(a, 0.f);
        }
    }
    __syncthreads();

    // sk softmax over 2 paths -> P, Q coefficients
#pragma unroll
    for (int i = 0; i < 2; i++) {
        int c = t + i * 256;
        float s0 = 0.f, s1 = 0.f;
        const float* w0 = w_sel + (size_t)c * ATTN;
        const float* w1 = w_sel + (size_t)(CC + c) * ATTN;
#pragma unroll
        for (int a = 0; a < ATTN; a++) { s0 += w0[a] * ssk[a]; s1 += w1[a] * ssk[a]; }
        float mx = fmaxf(s0, s1);
        float e0 = expf(s0 - mx), e1 = expf(s1 - mx);
        float inv = 1.f / (e0 + e1);
        float a0 = e0 * inv, a1 = e1 * inv;
        float ca = sca[c];
        g_P[b*CC + c] = a0 * ca + a1;   // coeff of spatial_attn
        g_Q[b*CC + c] = a1 * ca;        // constant part
    }
}

// ---------------- K4: ctx per pixel = v . x + c0 ; exp & sum ----------------
__global__ void k4_ctx(const float* __restrict__ x) {
    __shared__ float sv[CC];
    __shared__ float red[256];
    int b = blockIdx.x, chunk = blockIdx.y, t = threadIdx.x;
    for (int i = t; i < CC; i += 256) sv[i] = g_v[b*CC + i];
    __syncthreads();
    int h = chunk * 256 + t;
    const float* xb = x + (size_t)b * CC * HWN;
    float a = g_c0[b];
#pragma unroll 8
    for (int c = 0; c < CC; c++) a += sv[c] * xb[c * HWN + h];
    float e = expf(a);   // |ctx| <= ~6, safe
    g_E[b*HWN + h] = e;
    red[t] = e; __syncthreads();
    for (int s = 128; s > 0; s >>= 1) { if (t < s) red[t] += red[t + s]; __syncthreads(); }
    if (t == 0) atomicAdd(&g_Esum[b], red[0]);
}

// ---------------- K5: out = x * (1 + Q + P * spatial_attn) ----------------
__global__ void k5_final(const float* __restrict__ x, float* __restrict__ out) {
    int i4 = blockIdx.x * 256 + threadIdx.x;           // float4 index
    int h4 = i4 & 1023;                                // HW/4 = 1024
    int c  = (i4 >> 10) & 511;
    int b  = i4 >> 19;
    float4 xv = ((const float4*)x)[i4];
    float4 ev = ((const float4*)g_E)[b * (HWN/4) + h4];
    float inv = 1.f / g_Esum[b];
    float P = g_P[b*CC + c], Q = g_Q[b*CC + c];
    float base = 1.f + Q;
    float4 o;
    o.x = xv.x * (base + P * ev.x * inv);
    o.y = xv.y * (base + P * ev.y * inv);
    o.z = xv.z * (base + P * ev.z * inv);
    o.w = xv.w * (base + P * ev.w * inv);
    ((float4*)out)[i4] = o;
}

// ---------------- launch ----------------
extern "C" void kernel_launch(void* const* d_in, const int* in_sizes, int n_in,
                              void* d_out, int out_size) {
    const float* x     = (const float*)d_in[0];
    const float* w_qr  = (const float*)d_in[1];
    const float* b_qr  = (const float*)d_in[2];
    const float* w_vr  = (const float*)d_in[3];
    const float* b_vr  = (const float*)d_in[4];
    const float* w_up  = (const float*)d_in[5];
    const float* b_up  = (const float*)d_in[6];
    const float* ln_g  = (const float*)d_in[7];
    const float* ln_b  = (const float*)d_in[8];
    const float* w_ql  = (const float*)d_in[9];
    const float* b_ql  = (const float*)d_in[10];
    const float* w_vl  = (const float*)d_in[11];
    const float* b_vl  = (const float*)d_in[12];
    const float* w_red = (const float*)d_in[13];
    const float* bn_g  = (const float*)d_in[14];
    const float* bn_b  = (const float*)d_in[15];
    const float* bn_rm = (const float*)d_in[16];
    const float* bn_rv = (const float*)d_in[17];
    const float* w_sel = (const float*)d_in[18];
    float* out = (float*)d_out;

    k0_init<<<32, 256>>>();
    k1_mask_y<<<dim3(BB, 16), 256>>>(x, w_qr, b_qr);
    k2_gmax<<<dim3(BB, 32), 256>>>(x, w_ql);
    k3_small<<<BB, 256>>>(w_vr, b_vr, w_up, b_up, ln_g, ln_b, b_ql,
                          w_vl, b_vl, w_red, bn_g, bn_b, bn_rm, bn_rv, w_sel);
    k4_ctx<<<dim3(BB, 16), 256>>>(x);
    k5_final<<<(BB*CC*HWN/4)/256, 256>>>(x, out);
}

// round 3
// speedup vs baseline: 1.6176x; 1.3043x over previous
#include <cuda_runtime.h>
#include <cuda_bf16.h>

#define BB 16
#define CC 512
#define MM 256
#define HWN 4096
#define ATTN 32

// ---------------- scratch ----------------
__device__ float g_Y[BB*CC];
__device__ float g_S[BB];
__device__ float g_Gmax[BB*MM];
__device__ float g_ctx[BB*MM];
__device__ float g_up[BB*CC];
__device__ float g_v[BB*CC];
__device__ float g_c0[BB];
__device__ float g_P[BB*CC];
__device__ float g_Q[BB*CC];
__device__ float g_E[BB*HWN];
__device__ float g_Esum[BB];

__device__ __forceinline__ void atomicMaxF(float* addr, float v) {
    int old = __float_as_int(*addr);
    while (__int_as_float(old) < v) {
        int prev = atomicCAS((int*)addr, old, __float_as_int(v));
        if (prev == old) break;
        old = prev;
    }
}

__device__ __forceinline__ float blockSum256(float v, float* red) {
    int t = threadIdx.x, lane = t & 31, warp = t >> 5;
    __syncthreads();
#pragma unroll
    for (int o = 16; o; o >>= 1) v += __shfl_xor_sync(~0u, v, o);
    if (lane == 0) red[warp] = v;
    __syncthreads();
    if (warp == 0) {
        float s = (lane < 8) ? red[lane] : 0.f;
#pragma unroll
        for (int o = 4; o; o >>= 1) s += __shfl_xor_sync(~0u, s, o);
        if (lane == 0) red[0] = s;
    }
    __syncthreads();
    return red[0];
}
__device__ __forceinline__ float blockMax256(float v, float* red) {
    int t = threadIdx.x, lane = t & 31, warp = t >> 5;
    __syncthreads();
#pragma unroll
    for (int o = 16; o; o >>= 1) v = fmaxf(v, __shfl_xor_sync(~0u, v, o));
    if (lane == 0) red[warp] = v;
    __syncthreads();
    if (warp == 0) {
        float s = (lane < 8) ? red[lane] : __int_as_float(0xff800000u);
#pragma unroll
        for (int o = 4; o; o >>= 1) s = fmaxf(s, __shfl_xor_sync(~0u, s, o));
        if (lane == 0) red[0] = s;
    }
    __syncthreads();
    return red[0];
}

// ---------------- K0: init ----------------
__global__ void k0_init() {
    int i = blockIdx.x * 256 + threadIdx.x;
    if (i < BB*CC) g_Y[i] = 0.f;
    if (i < BB*MM) g_Gmax[i] = __int_as_float(0xff800000u);
    if (i < BB) { g_S[i] = 0.f; g_Esum[i] = 0.f; }
}

// ---------------- K12: block-specialized k1 (mask/Y) + k2 (tensor gmax) ----------------
// grid: [0,256) -> k1 role (b,chunk);  [256, 256+BB*64) -> k2 role (b, mt, nt)
#define K1_BLOCKS (BB*16)
__global__ __launch_bounds__(256, 2) void k12(const float* __restrict__ x,
                                              const float* __restrict__ w_qr,
                                              const float* __restrict__ b_qr,
                                              const float* __restrict__ w_ql) {
    __shared__ __align__(16) char smem_raw[2 * 128 * 40 * 2];  // 20.5KB
    int bid = blockIdx.x, t = threadIdx.x;

    if (bid < K1_BLOCKS) {
        // ===== k1 role =====
        float* sw   = (float*)smem_raw;            // [CC]
        float* se   = sw + CC;                      // [256]
        float* sred = se + 256;                     // [256]
        int b = bid >> 4, chunk = bid & 15;
        for (int i = t; i < CC; i += 256) sw[i] = w_qr[i];
        __syncthreads();

        int h = chunk * 256 + t;
        const float* xb = x + (size_t)b * CC * HWN;
        const float* xp = xb + h;
        float l0 = 0.f, l1 = 0.f, l2 = 0.f, l3 = 0.f;
#pragma unroll 4
        for (int c = 0; c < CC; c += 4) {
            l0 += sw[c]     * xp[(size_t)c * HWN];
            l1 += sw[c + 1] * xp[(size_t)(c + 1) * HWN];
            l2 += sw[c + 2] * xp[(size_t)(c + 2) * HWN];
            l3 += sw[c + 3] * xp[(size_t)(c + 3) * HWN];
        }
        float e = expf(b_qr[0] + (l0 + l1) + (l2 + l3));
        se[t] = e;
        sred[t] = e;
        __syncthreads();
        for (int s = 128; s > 0; s >>= 1) { if (t < s) sred[t] += sred[t + s]; __syncthreads(); }
        if (t == 0) atomicAdd(&g_S[b], sred[0]);

        const float4* se4 = (const float4*)se;
        for (int cc = t; cc < CC; cc += 256) {
            const float4* xr = (const float4*)(xb + (size_t)cc * HWN + chunk * 256);
            float a0 = 0.f, a1 = 0.f;
#pragma unroll 8
            for (int j = 0; j < 64; j += 2) {
                float4 xv = xr[j];     float4 ev = se4[j];
                a0 += ev.x*xv.x + ev.y*xv.y + ev.z*xv.z + ev.w*xv.w;
                float4 xw = xr[j + 1]; float4 ew = se4[j + 1];
                a1 += ew.x*xw.x + ew.y*xw.y + ew.z*xw.z + ew.w*xw.w;
            }
            atomicAdd(&g_Y[b*CC + cc], a0 + a1);
        }
    } else {
        // ===== k2 role: 128(M) x 128(N) tile, K=512, bf16 mma =====
        __nv_bfloat16 (*As)[40] = (__nv_bfloat16(*)[40])smem_raw;
        __nv_bfloat16 (*Bs)[40] = (__nv_bfloat16(*)[40])(smem_raw + 128 * 40 * 2);
        int bid2 = bid - K1_BLOCKS;
        int b = bid2 >> 6, r6 = bid2 & 63;
        int mt = r6 >> 5, nt = r6 & 31;
        int warp = t >> 5, lane = t & 31;
        int wm = warp >> 2, wn = warp & 3;          // 2 x 4 warps; warp tile 64x32
        const float* xb = x + (size_t)b * CC * HWN + nt * 128;
        const float* wq = w_ql + (size_t)mt * 128 * CC;

        float acc[4][4][4];
#pragma unroll
        for (int i = 0; i < 4; i++)
#pragma unroll
            for (int j = 0; j < 4; j++)
#pragma unroll
                for (int k = 0; k < 4; k++) acc[i][j][k] = 0.f;

        for (int k0 = 0; k0 < CC; k0 += 32) {
            __syncthreads();
#pragma unroll
            for (int p = 0; p < 16; p++) {          // A: 128x32
                int i = t + p * 256;
                int m = i >> 5, k = i & 31;
                As[m][k] = __float2bfloat16(wq[m * CC + k0 + k]);
            }
#pragma unroll
            for (int p = 0; p < 16; p++) {          // B: 32x128 -> Bs[n][k]
                int i = t + p * 256;
                int n = i & 127, k = i >> 7;
                Bs[n][k] = __float2bfloat16(xb[(size_t)(k0 + k) * HWN + n]);
            }
            __syncthreads();
#pragma unroll
            for (int kb = 0; kb < 32; kb += 16) {
                unsigned af[4][4], bf[4][2];
                int cq = kb + (lane & 3) * 2;
#pragma unroll
                for (int mf = 0; mf < 4; mf++) {
                    int r = wm * 64 + mf * 16 + (lane >> 2);
                    af[mf][0] = *(const unsigned*)&As[r][cq];
                    af[mf][1] = *(const unsigned*)&As[r + 8][cq];
                    af[mf][2] = *(const unsigned*)&As[r][cq + 8];
                    af[mf][3] = *(const unsigned*)&As[r + 8][cq + 8];
                }
#pragma unroll
                for (int nf = 0; nf < 4; nf++) {
                    int n = wn * 32 + nf * 8 + (lane >> 2);
                    bf[nf][0] = *(const unsigned*)&Bs[n][cq];
                    bf[nf][1] = *(const unsigned*)&Bs[n][cq + 8];
                }
#pragma unroll
                for (int mf = 0; mf < 4; mf++)
#pragma unroll
                    for (int nf = 0; nf < 4; nf++)
                        asm volatile(
                            "mma.sync.aligned.m16n8k16.row.col.f32.bf16.bf16.f32 "
                            "{%0,%1,%2,%3}, {%4,%5,%6,%7}, {%8,%9}, {%0,%1,%2,%3};\n"
                            : "+f"(acc[mf][nf][0]), "+f"(acc[mf][nf][1]),
                              "+f"(acc[mf][nf][2]), "+f"(acc[mf][nf][3])
                            : "r"(af[mf][0]), "r"(af[mf][1]), "r"(af[mf][2]), "r"(af[mf][3]),
                              "r"(bf[nf][0]), "r"(bf[nf][1]));
            }
        }
#pragma unroll
        for (int mf = 0; mf < 4; mf++) {
            float m0 = __int_as_float(0xff800000u), m1 = m0;
#pragma unroll
            for (int nf = 0; nf < 4; nf++) {
                m0 = fmaxf(m0, fmaxf(acc[mf][nf][0], acc[mf][nf][1]));
                m1 = fmaxf(m1, fmaxf(acc[mf][nf][2], acc[mf][nf][3]));
            }
            m0 = fmaxf(m0, __shfl_xor_sync(~0u, m0, 1));
            m0 = fmaxf(m0, __shfl_xor_sync(~0u, m0, 2));
            m1 = fmaxf(m1, __shfl_xor_sync(~0u, m1, 1));
            m1 = fmaxf(m1, __shfl_xor_sync(~0u, m1, 2));
            if ((lane & 3) == 0) {
                int r = mt * 128 + wm * 64 + mf * 16 + (lane >> 2);
                atomicMaxF(&g_Gmax[b * MM + r], m0);
                atomicMaxF(&g_Gmax[b * MM + r + 8], m1);
            }
        }
    }
}

// ---------------- K3a: context = W_vr @ (Y/S) + b_vr.  grid (B, 8) ----------------
__global__ void k3a(const float* __restrict__ w_vr, const float* __restrict__ b_vr) {
    __shared__ float sy[CC];
    int b = blockIdx.x, blk = blockIdx.y, t = threadIdx.x;
    int warp = t >> 5, lane = t & 31;
    float Sinv = 1.f / g_S[b];
    for (int i = t; i < CC; i += 256) sy[i] = g_Y[b*CC + i] * Sinv;
    __syncthreads();
#pragma unroll
    for (int i = 0; i < 4; i++) {
        int r = blk * 32 + warp * 4 + i;
        const float* wr = w_vr + (size_t)r * CC;
        float a = 0.f;
#pragma unroll
        for (int c = lane; c < CC; c += 32) a += wr[c] * sy[c];
#pragma unroll
        for (int o = 16; o; o >>= 1) a += __shfl_xor_sync(~0u, a, o);
        if (lane == 0) g_ctx[b*MM + r] = a + b_vr[r];
    }
}

// ---------------- K3b: up = W_up @ ctx + b_up.  grid (B, 16) ----------------
__global__ void k3b(const float* __restrict__ w_up, const float* __restrict__ b_up) {
    __shared__ float sc[MM];
    int b = blockIdx.x, blk = blockIdx.y, t = threadIdx.x;
    int warp = t >> 5, lane = t & 31;
    if (t < MM) sc[t] = g_ctx[b*MM + t];
    __syncthreads();
#pragma unroll
    for (int i = 0; i < 4; i++) {
        int r = blk * 32 + warp * 4 + i;
        const float* wr = w_up + (size_t)r * MM;
        float a = 0.f;
#pragma unroll
        for (int m = lane; m < MM; m += 32) a += wr[m] * sc[m];
#pragma unroll
        for (int o = 16; o; o >>= 1) a += __shfl_xor_sync(~0u, a, o);
        if (lane == 0) g_up[b*CC + r] = a + b_up[r];
    }
}

// ---------------- K3c: per-batch tail.  grid B ----------------
__global__ void k3c(const float* __restrict__ ln_g, const float* __restrict__ ln_b,
                    const float* __restrict__ b_ql,
                    const float* __restrict__ w_vl, const float* __restrict__ b_vl,
                    const float* __restrict__ w_red, const float* __restrict__ bn_g,
                    const float* __restrict__ bn_b, const float* __restrict__ bn_rm,
                    const float* __restrict__ bn_rv, const float* __restrict__ w_sel) {
    __shared__ float sy[CC];
    __shared__ float sca[CC];
    __shared__ float savg[MM];
    __shared__ float ssk[ATTN];
    __shared__ float red[8];
    int b = blockIdx.x, t = threadIdx.x;
    int warp = t >> 5, lane = t & 31;

    // LayerNorm + sigmoid
    float u0 = g_up[b*CC + t], u1 = g_up[b*CC + t + 256];
    float mean = blockSum256(u0 + u1, red) * (1.f / CC);
    float var  = blockSum256(u0*u0 + u1*u1, red) * (1.f / CC) - mean * mean;
    float rstd = rsqrtf(var + 1e-5f);
    sca[t]       = 1.f / (1.f + expf(-((u0 - mean) * rstd * ln_g[t] + ln_b[t])));
    sca[t + 256] = 1.f / (1.f + expf(-((u1 - mean) * rstd * ln_g[t + 256] + ln_b[t + 256])));

    // avg = softmax(Gmax + b_ql)
    float gv = g_Gmax[b*MM + t] + b_ql[t];
    float gm = blockMax256(gv, red);
    float ge = expf(gv - gm);
    float gs = blockSum256(ge, red);
    savg[t] = ge / gs;
    float c0 = blockSum256((ge / gs) * b_vl[t], red);
    if (t == 0) g_c0[b] = c0;
    __syncthreads();

    // v[c] = sum_m avg[m] * w_vl[m,c]
    {
        float a0 = 0.f, a1 = 0.f;
#pragma unroll 8
        for (int m = 0; m < MM; m++) {
            float av = savg[m];
            const float* wr = w_vl + (size_t)m * CC;
            a0 += av * wr[t];
            a1 += av * wr[t + 256];
        }
        g_v[b*CC + t]       = a0;
        g_v[b*CC + t + 256] = a1;
    }

    // s[c] = ca*(1+1/HW) + 1/HW
    const float invHW = 1.f / (float)HWN;
    sy[t]       = sca[t]       * (1.f + invHW) + invHW;
    sy[t + 256] = sca[t + 256] * (1.f + invHW) + invHW;
    __syncthreads();

    // relu(bn(W_red @ s))
#pragma unroll
    for (int i = 0; i < 4; i++) {
        int r = warp * 4 + i;
        const float* wr = w_red + (size_t)r * CC;
        float a = 0.f;
#pragma unroll
        for (int c = lane; c < CC; c += 32) a += wr[c] * sy[c];
#pragma unroll
        for (int o = 16; o; o >>= 1) a += __shfl_xor_sync(~0u, a, o);
        if (lane == 0) {
            a = (a - bn_rm[r]) * rsqrtf(bn_rv[r] + 1e-5f) * bn_g[r] + bn_b[r];
            ssk[r] = fmaxf(a, 0.f);
        }
    }
    __syncthreads();

    // sk softmax -> P, Q
#pragma unroll
    for (int i = 0; i < 2; i++) {
        int c = t + i * 256;
        float s0 = 0.f, s1 = 0.f;
        const float* w0 = w_sel + (size_t)c * ATTN;
        const float* w1 = w_sel + (size_t)(CC + c) * ATTN;
#pragma unroll
        for (int a = 0; a < ATTN; a++) { s0 += w0[a] * ssk[a]; s1 += w1[a] * ssk[a]; }
        float mx = fmaxf(s0, s1);
        float e0 = expf(s0 - mx), e1 = expf(s1 - mx);
        float inv = 1.f / (e0 + e1);
        float a0 = e0 * inv, a1 = e1 * inv;
        float ca = sca[c];
        g_P[b*CC + c] = a0 * ca + a1;
        g_Q[b*CC + c] = a1 * ca;
    }
}

// ---------------- K4: ctx per pixel = v.x + c0; exp & sum ----------------
__global__ void k4_ctx(const float* __restrict__ x) {
    __shared__ float sv[CC];
    __shared__ float red[256];
    int b = blockIdx.x, chunk = blockIdx.y, t = threadIdx.x;
    for (int i = t; i < CC; i += 256) sv[i] = g_v[b*CC + i];
    __syncthreads();
    int h = chunk * 256 + t;
    const float* xp = x + (size_t)b * CC * HWN + h;
    float a0 = 0.f, a1 = 0.f, a2 = 0.f, a3 = 0.f;
#pragma unroll 4
    for (int c = 0; c < CC; c += 4) {
        a0 += sv[c]     * xp[(size_t)c * HWN];
        a1 += sv[c + 1] * xp[(size_t)(c + 1) * HWN];
        a2 += sv[c + 2] * xp[(size_t)(c + 2) * HWN];
        a3 += sv[c + 3] * xp[(size_t)(c + 3) * HWN];
    }
    float e = expf(g_c0[b] + (a0 + a1) + (a2 + a3));
    g_E[b*HWN + h] = e;
    red[t] = e; __syncthreads();
    for (int s = 128; s > 0; s >>= 1) { if (t < s) red[t] += red[t + s]; __syncthreads(); }
    if (t == 0) atomicAdd(&g_Esum[b], red[0]);
}

// ---------------- K5: out = x * (1 + Q + P * spatial_attn) ----------------
__global__ void k5_final(const float* __restrict__ x, float* __restrict__ out) {
    int i4 = blockIdx.x * 256 + threadIdx.x;
    int h4 = i4 & 1023;
    int c  = (i4 >> 10) & 511;
    int b  = i4 >> 19;
    float4 xv = ((const float4*)x)[i4];
    float4 ev = ((const float4*)g_E)[b * (HWN/4) + h4];
    float inv = 1.f / g_Esum[b];
    float P = g_P[b*CC + c], Q = g_Q[b*CC + c];
    float base = 1.f + Q;
    float4 o;
    o.x = xv.x * (base + P * ev.x * inv);
    o.y = xv.y * (base + P * ev.y * inv);
    o.z = xv.z * (base + P * ev.z * inv);
    o.w = xv.w * (base + P * ev.w * inv);
    ((float4*)out)[i4] = o;
}

// ---------------- launch ----------------
extern "C" void kernel_launch(void* const* d_in, const int* in_sizes, int n_in,
                              void* d_out, int out_size) {
    const float* x     = (const float*)d_in[0];
    const float* w_qr  = (const float*)d_in[1];
    const float* b_qr  = (const float*)d_in[2];
    const float* w_vr  = (const float*)d_in[3];
    const float* b_vr  = (const float*)d_in[4];
    const float* w_up  = (const float*)d_in[5];
    const float* b_up  = (const float*)d_in[6];
    const float* ln_g  = (const float*)d_in[7];
    const float* ln_b  = (const float*)d_in[8];
    const float* w_ql  = (const float*)d_in[9];
    const float* b_ql  = (const float*)d_in[10];
    const float* w_vl  = (const float*)d_in[11];
    const float* b_vl  = (const float*)d_in[12];
    const float* w_red = (const float*)d_in[13];
    const float* bn_g  = (const float*)d_in[14];
    const float* bn_b  = (const float*)d_in[15];
    const float* bn_rm = (const float*)d_in[16];
    const float* bn_rv = (const float*)d_in[17];
    const float* w_sel = (const float*)d_in[18];
    float* out = (float*)d_out;

    k0_init<<<32, 256>>>();
    k12<<<K1_BLOCKS + BB*64, 256>>>(x, w_qr, b_qr, w_ql);
    k3a<<<dim3(BB, 8), 256>>>(w_vr, b_vr);
    k3b<<<dim3(BB, 16), 256>>>(w_up, b_up);
    k3c<<<BB, 256>>>(ln_g, ln_b, b_ql, w_vl, b_vl, w_red, bn_g, bn_b, bn_rm, bn_rv, w_sel);
    k4_ctx<<<dim3(BB, 16), 256>>>(x);
    k5_final<<<(BB*CC*HWN/4)/256, 256>>>(x, out);
}